// round 7
// baseline (speedup 1.0000x reference)
#include <cuda_runtime.h>
#include <cuda_bf16.h>
#include <cstdint>
#include <cstddef>

#define BATCH 1024
#define HW 1024   // 32*32

// ---------------- scratch (device globals; no allocs allowed) ----------------
__device__ __nv_bfloat16 g_Hhi[(size_t)BATCH * HW * 64];  // 128 MB each
__device__ __nv_bfloat16 g_Hlo[(size_t)BATCH * HW * 64];
__device__ __nv_bfloat16 g_Rhi[(size_t)BATCH * HW * 64];
__device__ __nv_bfloat16 g_Rlo[(size_t)BATCH * HW * 64];
__device__ __nv_bfloat16 g_Whi[4 * 9 * 64 * 72];
__device__ __nv_bfloat16 g_Wlo[4 * 9 * 64 * 72];
__device__ float g_gap[BATCH * 64];
__device__ int   g_flag[BATCH];

// ---------------- misc ----------------
__global__ void zero_conf(float* conf) {
    int t = threadIdx.x;
    if (t < 100) conf[t] = 0.0f;
}

// ci-word permutation: natural word n (pair of ci) -> position word
//   within 8-word group: k<4 -> 2k ; k>=4 -> 2(k-4)+1
// prep_w emits weights already permuted; all activation producers write permuted.
__global__ void prep_w(const float* __restrict__ w, __nv_bfloat16* __restrict__ whi,
                       __nv_bfloat16* __restrict__ wlo) {
    int idx = blockIdx.x * 256 + threadIdx.x;          // 9*64*72 = 41472 (position space)
    if (idx >= 9 * 64 * 72) return;
    int s = idx / (64 * 72), rem = idx % (64 * 72), co = rem / 72, cip = rem % 72;
    int p = cip >> 1, g = p >> 3, pw = p & 7;
    int k = (pw & 1) ? ((pw - 1) >> 1) + 4 : (pw >> 1);
    int nat_ci = (g * 8 + k) * 2 + (cip & 1);
    float v = 0.0f;
    if (nat_ci < 64) v = w[(co * 64 + nat_ci) * 9 + s];
    __nv_bfloat16 h = __float2bfloat16(v);
    whi[idx] = h;
    wlo[idx] = __float2bfloat16(v - __bfloat162float(h));
}

// ---------------- fused LeNet: conv1+pool, conv2+pool, FCs, argmax/softmax/conf ----------------
__global__ __launch_bounds__(256) void lenet_all(
        const float* __restrict__ x, const float* __restrict__ w1, const float* __restrict__ b1,
        const float* __restrict__ w2, const float* __restrict__ b2,
        const float* __restrict__ fc1w, const float* __restrict__ fc1b,
        const float* __restrict__ fc2w, const float* __restrict__ fc2b,
        const float* __restrict__ fc3w, const float* __restrict__ fc3b,
        const float* __restrict__ thr_p, const int* __restrict__ labels,
        float* __restrict__ lenout, float* conf, int* __restrict__ flag) {
    __shared__ float sx[3 * 32 * 32];
    __shared__ float sw[2400];
    __shared__ float p1[1176];
    __shared__ float p2[400];
    __shared__ float h1[120];
    __shared__ float h2[84];
    __shared__ float lg[10];
    __shared__ float sb[16];
    int bid = blockIdx.x, t = threadIdx.x;
    const float* xb = x + (size_t)bid * 3072;
    for (int i = t; i < 3072; i += 256) sx[i] = xb[i];
    for (int i = t; i < 450; i += 256) sw[i] = w1[i];
    if (t < 6) sb[t] = b1[t];
    __syncthreads();
    for (int idx = t; idx < 6 * 14 * 14; idx += 256) {
        int c = idx / 196, py = (idx / 14) % 14, px = idx % 14;
        float m = -1e30f;
        #pragma unroll
        for (int dy = 0; dy < 2; dy++)
            #pragma unroll
            for (int dx = 0; dx < 2; dx++) {
                int y = 2 * py + dy, x0 = 2 * px + dx;
                float a = sb[c];
                for (int ci = 0; ci < 3; ci++)
                    #pragma unroll
                    for (int ky = 0; ky < 5; ky++)
                        #pragma unroll
                        for (int kx = 0; kx < 5; kx++)
                            a = fmaf(sx[ci * 1024 + (y + ky) * 32 + (x0 + kx)],
                                     sw[(c * 3 + ci) * 25 + ky * 5 + kx], a);
                m = fmaxf(m, a);
            }
        p1[idx] = fmaxf(m, 0.0f);
    }
    __syncthreads();
    for (int i = t; i < 2400; i += 256) sw[i] = w2[i];
    if (t < 16) sb[t] = b2[t];
    __syncthreads();
    for (int idx = t; idx < 400; idx += 256) {
        int c = idx / 25, py = (idx / 5) % 5, px = idx % 5;
        float m = -1e30f;
        #pragma unroll
        for (int dy = 0; dy < 2; dy++)
            #pragma unroll
            for (int dx = 0; dx < 2; dx++) {
                int y = 2 * py + dy, x0 = 2 * px + dx;
                float a = sb[c];
                for (int ci = 0; ci < 6; ci++)
                    #pragma unroll
                    for (int ky = 0; ky < 5; ky++)
                        #pragma unroll
                        for (int kx = 0; kx < 5; kx++)
                            a = fmaf(p1[ci * 196 + (y + ky) * 14 + (x0 + kx)],
                                     sw[(c * 6 + ci) * 25 + ky * 5 + kx], a);
                m = fmaxf(m, a);
            }
        p2[idx] = fmaxf(m, 0.0f);
    }
    __syncthreads();
    if (t < 120) {
        float a = fc1b[t];
        for (int k = 0; k < 400; k++) a = fmaf(p2[k], fc1w[k * 120 + t], a);
        h1[t] = fmaxf(a, 0.0f);
    }
    __syncthreads();
    if (t < 84) {
        float a = fc2b[t];
        for (int k = 0; k < 120; k++) a = fmaf(h1[k], fc2w[k * 84 + t], a);
        h2[t] = fmaxf(a, 0.0f);
    }
    __syncthreads();
    if (t < 10) {
        float a = fc3b[t];
        for (int k = 0; k < 84; k++) a = fmaf(h2[k], fc3w[k * 10 + t], a);
        lg[t] = a;
        lenout[(size_t)bid * 10 + t] = a;
    }
    __syncthreads();
    if (t == 0) {
        float m = lg[0]; int am = 0;
        #pragma unroll
        for (int i = 1; i < 10; i++) if (lg[i] > m) { m = lg[i]; am = i; }
        float p[10]; float s = 0.0f;
        #pragma unroll
        for (int i = 0; i < 10; i++) { p[i] = expf(lg[i] - m); s += p[i]; }
        float inv = 1.0f / s;
        float p0 = -1.0f, pp1 = -1.0f;
        #pragma unroll
        for (int i = 0; i < 10; i++) {
            float v = p[i] * inv;
            if (v > p0) { pp1 = p0; p0 = v; } else if (v > pp1) { pp1 = v; }
        }
        flag[bid] = ((p0 - pp1) <= thr_p[0]) ? 1 : 0;
        atomicAdd(&conf[labels[bid] * 10 + am], 1.0f);
    }
}

// ---------------- split helper ----------------
__device__ __forceinline__ void split_bf16(float v, __nv_bfloat16& h, __nv_bfloat16& l) {
    h = __float2bfloat16(v);
    l = __float2bfloat16(v - __bfloat162float(h));
}

// ---------------- ResNet conv0 (3->64, fp32 direct), hi/lo NHWC (permuted words) ----------------
__global__ __launch_bounds__(256, 2) void conv0_k(const float* __restrict__ x,
        const float* __restrict__ w, const float* __restrict__ bias,
        __nv_bfloat16* __restrict__ ohi, __nv_bfloat16* __restrict__ olo) {
    __shared__ __align__(16) float s_in[3 * 10 * 36];
    __shared__ float s_w[3 * 64 * 9];
    int b = blockIdx.x, row0 = blockIdx.y * 8;
    int t = threadIdx.x, warp = t >> 5, lane = t & 31;
    int r2 = lane >> 3, colg = lane & 7, cob = warp * 8;

    float acc[2][4][8];
    #pragma unroll
    for (int oc = 0; oc < 8; oc++) {
        float bv = bias[cob + oc];
        #pragma unroll
        for (int rr = 0; rr < 2; rr++)
            #pragma unroll
            for (int cc = 0; cc < 4; cc++) acc[rr][cc][oc] = bv;
    }
    const float* inb = x + (size_t)b * 3 * HW;
    for (int idx = t; idx < 3 * 340; idx += 256) {
        int kc = idx / 340, rem = idx % 340, r = rem / 34, c = rem % 34;
        int gr = row0 - 1 + r, gc = c - 1;
        float v = 0.0f;
        if ((unsigned)gr < 32u && (unsigned)gc < 32u)
            v = inb[(size_t)kc * HW + gr * 32 + gc];
        s_in[kc * 360 + r * 36 + c] = v;
    }
    for (int idx = t; idx < 3 * 576; idx += 256) {
        int kc = idx / 576, rem = idx % 576, co = rem / 9, k = rem % 9;
        s_w[idx] = w[((size_t)co * 3 + kc) * 9 + k];
    }
    __syncthreads();
    #pragma unroll
    for (int kc = 0; kc < 3; kc++) {
        float xin[4][6];
        const float* sbase = s_in + kc * 360 + (r2 * 2) * 36 + colg * 4;
        #pragma unroll
        for (int r = 0; r < 4; r++) {
            float4 a = *reinterpret_cast<const float4*>(sbase + r * 36);
            float2 bv = *reinterpret_cast<const float2*>(sbase + r * 36 + 4);
            xin[r][0] = a.x; xin[r][1] = a.y; xin[r][2] = a.z; xin[r][3] = a.w;
            xin[r][4] = bv.x; xin[r][5] = bv.y;
        }
        const float* wp = s_w + kc * 576 + cob * 9;
        #pragma unroll
        for (int oc = 0; oc < 8; oc++) {
            float w0 = wp[oc * 9], w1 = wp[oc * 9 + 1], w2 = wp[oc * 9 + 2];
            float w3 = wp[oc * 9 + 3], w4 = wp[oc * 9 + 4], w5 = wp[oc * 9 + 5];
            float w6 = wp[oc * 9 + 6], w7 = wp[oc * 9 + 7], w8 = wp[oc * 9 + 8];
            #pragma unroll
            for (int rr = 0; rr < 2; rr++)
                #pragma unroll
                for (int cc = 0; cc < 4; cc++) {
                    float a = acc[rr][cc][oc];
                    a = fmaf(xin[rr][cc],     w0, a);
                    a = fmaf(xin[rr][cc + 1], w1, a);
                    a = fmaf(xin[rr][cc + 2], w2, a);
                    a = fmaf(xin[rr + 1][cc],     w3, a);
                    a = fmaf(xin[rr + 1][cc + 1], w4, a);
                    a = fmaf(xin[rr + 1][cc + 2], w5, a);
                    a = fmaf(xin[rr + 2][cc],     w6, a);
                    a = fmaf(xin[rr + 2][cc + 1], w7, a);
                    a = fmaf(xin[rr + 2][cc + 2], w8, a);
                    acc[rr][cc][oc] = a;
                }
        }
    }
    // permuted-word epilogue: warp owns natural words cob/2..cob/2+3 (k = h*4+j2)
    size_t ob = (size_t)b * HW * 64;
    int g = cob >> 4, h = (cob >> 3) & 1;
    #pragma unroll
    for (int rr = 0; rr < 2; rr++)
        #pragma unroll
        for (int cc = 0; cc < 4; cc++) {
            int px = (row0 + r2 * 2 + rr) * 32 + colg * 4 + cc;
            size_t pxb = ob + (size_t)px * 64;
            #pragma unroll
            for (int j2 = 0; j2 < 4; j2++) {
                int pos = g * 8 + 2 * j2 + h;            // position word
                __nv_bfloat16 h0, l0, h1v, l1v;
                split_bf16(fmaxf(acc[rr][cc][2 * j2],     0.f), h0,  l0);
                split_bf16(fmaxf(acc[rr][cc][2 * j2 + 1], 0.f), h1v, l1v);
                *reinterpret_cast<__nv_bfloat162*>(ohi + pxb + pos * 2) =
                    __halves2bfloat162(h0, h1v);
                *reinterpret_cast<__nv_bfloat162*>(olo + pxb + pos * 2) =
                    __halves2bfloat162(l0, l1v);
            }
        }
}

// ---------------- bf16x3 tensor-core 3x3 SAME conv, 64->64, hi/lo NHWC (permuted) ----------------
__device__ __forceinline__ void mma_bf16(float* d, uint32_t a0, uint32_t a1, uint32_t a2,
                                         uint32_t a3, uint32_t b0, uint32_t b1) {
    asm volatile("mma.sync.aligned.m16n8k16.row.col.f32.bf16.bf16.f32 "
                 "{%0,%1,%2,%3}, {%4,%5,%6,%7}, {%8,%9}, {%0,%1,%2,%3};"
                 : "+f"(d[0]), "+f"(d[1]), "+f"(d[2]), "+f"(d[3])
                 : "r"(a0), "r"(a1), "r"(a2), "r"(a3), "r"(b0), "r"(b1));
}

#define IN_PITCH 36                 // words per px row (64 ci bf16 data + pad)
#define PLANE    7344               // 204 px (6 rows x 34 cols) * 36 words
#define WOFF     14688              // W buffers start (words)
#define WPLANE   2304               // 64 co * 36 words
#define SMEM_WORDS (WOFF + 2 * 2 * WPLANE)          // 23904
#define SMEM_BYTES (SMEM_WORDS * 4)                 // 95616

__global__ __launch_bounds__(256, 2) void conv_mma(
        const __nv_bfloat16* __restrict__ inhi,   // [B][1024][64] permuted words
        const __nv_bfloat16* __restrict__ inlo,
        const __nv_bfloat16* __restrict__ whi,    // [9][64][72] permuted words
        const __nv_bfloat16* __restrict__ wlo,
        const float* __restrict__ bias,
        const __nv_bfloat16* reshi, const __nv_bfloat16* reslo,
        __nv_bfloat16* __restrict__ outhi, __nv_bfloat16* __restrict__ outlo) {
    extern __shared__ uint32_t sm[];
    int b = blockIdx.x, g = blockIdx.y, r0 = g * 4;
    int t = threadIdx.x, lane = t & 31, warp = t >> 5;
    int cogrp = warp >> 1, pxhalf = warp & 1;
    int pxbase = pxhalf * 64, cobase = cogrp * 16;

    // ---- stage input tile via cp.async: 6 rows x 34 cols, hi+lo planes ----
    const __nv_bfloat16* hbase = inhi + (size_t)b * HW * 64;
    const __nv_bfloat16* lbase = inlo + (size_t)b * HW * 64;
    for (int idx = t; idx < 3264; idx += 256) {          // 2 planes * 204 px * 8 chunks
        int plane = idx >= 1632;
        int rem = idx - plane * 1632;
        int pxt = rem >> 3, ck = rem & 7;
        int rt = pxt / 34, ct = pxt % 34;
        int gr = r0 - 1 + rt, gc = ct - 1;
        int ok = ((unsigned)gr < 32u) && ((unsigned)gc < 32u);
        const __nv_bfloat16* base = plane ? lbase : hbase;
        const char* src = reinterpret_cast<const char*>(
            base + (ok ? ((size_t)(gr * 32 + gc)) * 64 + ck * 8 : 0));
        uint32_t dst = (uint32_t)__cvta_generic_to_shared(
            sm + plane * PLANE + pxt * IN_PITCH + ck * 4);
        int sz = ok ? 16 : 0;
        asm volatile("cp.async.ca.shared.global [%0], [%1], 16, %2;"
                     :: "r"(dst), "l"(src), "r"(sz));
    }

    // ---- cp.async weight staging, per shift, double buffered ----
    auto issueW = [&](int s, int buf) {
        for (int c = t; c < 1152; c += 256) {            // 2 planes * 576 16B chunks
            int plane = (c >= 576) ? 1 : 0;
            int cc = c - plane * 576;
            const char* src = reinterpret_cast<const char*>(plane ? wlo : whi)
                              + (size_t)s * 9216 + cc * 16;
            uint32_t dst = (uint32_t)__cvta_generic_to_shared(
                sm + WOFF + buf * (2 * WPLANE) + plane * WPLANE + cc * 4);
            asm volatile("cp.async.ca.shared.global [%0], [%1], 16;" :: "r"(dst), "l"(src));
        }
        asm volatile("cp.async.commit_group;" ::: "memory");
    };
    issueW(0, 0);

    // ---- accumulators + per-thread base offsets (permuted word space) ----
    float bl = bias[cobase + (lane >> 2)], bh = bias[cobase + (lane >> 2) + 8];
    float acc[8][4];
    #pragma unroll
    for (int j = 0; j < 8; j++) { acc[j][0] = bl; acc[j][1] = bl; acc[j][2] = bh; acc[j][3] = bh; }
    int bword[8];
    #pragma unroll
    for (int j = 0; j < 8; j++) {
        int p = pxbase + j * 8 + (lane >> 2);
        int r = p >> 5, c = p & 31;
        bword[j] = (r * 34 + c) * IN_PITCH + 2 * (lane & 3);   // LDS.64 base
    }
    int awbase = (cobase + (lane >> 2)) * IN_PITCH + 2 * (lane & 3);

    // ---- main loop over 9 shifts ----
    for (int s = 0; s < 9; s++) {
        int buf = s & 1;
        asm volatile("cp.async.wait_group 0;" ::: "memory");
        __syncthreads();
        if (s < 8) issueW(s + 1, buf ^ 1);
        int ky = s / 3, kx = s - 3 * ky;
        int soff = (ky * 34 + kx) * IN_PITCH;
        const uint32_t* wh = sm + WOFF + buf * (2 * WPLANE);
        const uint32_t* wl = wh + WPLANE;
        const uint32_t* ih = sm;
        const uint32_t* il = sm + PLANE;
        #pragma unroll
        for (int q = 0; q < 4; q++) {
            int aw = awbase + q * 8;
            // (a0,a2) at row, (a1,a3) at row+8, each one LDS.64
            uint2 uh0 = *reinterpret_cast<const uint2*>(wh + aw);
            uint2 uh1 = *reinterpret_cast<const uint2*>(wh + aw + 8 * IN_PITCH);
            uint2 ul0 = *reinterpret_cast<const uint2*>(wl + aw);
            uint2 ul1 = *reinterpret_cast<const uint2*>(wl + aw + 8 * IN_PITCH);
            #pragma unroll
            for (int j = 0; j < 8; j++) {
                int bw = bword[j] + soff + q * 8;
                uint2 bhv = *reinterpret_cast<const uint2*>(ih + bw);   // (b0,b1) hi
                uint2 blv = *reinterpret_cast<const uint2*>(il + bw);   // (b0,b1) lo
                mma_bf16(acc[j], uh0.x, uh1.x, uh0.y, uh1.y, bhv.x, bhv.y);
                mma_bf16(acc[j], uh0.x, uh1.x, uh0.y, uh1.y, blv.x, blv.y);
                mma_bf16(acc[j], ul0.x, ul1.x, ul0.y, ul1.y, bhv.x, bhv.y);
            }
        }
    }

    // ---- epilogue: transpose through smem (fp32, pitch 68), then coalesced out ----
    float* smf = reinterpret_cast<float*>(sm);
    __syncthreads();
    {
        int col = cobase + (lane >> 2);
        #pragma unroll
        for (int j = 0; j < 8; j++) {
            int p0 = pxbase + j * 8 + (lane & 3) * 2;
            smf[p0 * 68 + col]            = acc[j][0];
            smf[(p0 + 1) * 68 + col]      = acc[j][1];
            smf[p0 * 68 + col + 8]        = acc[j][2];
            smf[(p0 + 1) * 68 + col + 8]  = acc[j][3];
        }
    }
    __syncthreads();
    // 128 px * 16 (gq,kq) units; unit (gq,kq) covers natural co {gq*16+2kq,+1,+8,+9}
    // -> position words gq*8+2kq, gq*8+2kq+1 (one uint2 per plane)
    size_t obase = ((size_t)b * HW + g * 128) * 64;
    for (int idx = t; idx < 2048; idx += 256) {
        int px = idx >> 4, rem = idx & 15, gq = rem >> 2, kq = rem & 3;
        int cn = gq * 16 + 2 * kq;
        const float* sp = smf + px * 68;
        float v0 = sp[cn], v1 = sp[cn + 1], v2 = sp[cn + 8], v3 = sp[cn + 9];
        size_t go = obase + (size_t)px * 64 + (gq * 8 + 2 * kq) * 2;   // bf16 index
        if (reshi) {
            uint2 rh = *reinterpret_cast<const uint2*>(reshi + go);
            uint2 rl = *reinterpret_cast<const uint2*>(reslo + go);
            const __nv_bfloat162* h2 = reinterpret_cast<const __nv_bfloat162*>(&rh);
            const __nv_bfloat162* l2 = reinterpret_cast<const __nv_bfloat162*>(&rl);
            float2 a0 = __bfloat1622float2(h2[0]), a1 = __bfloat1622float2(h2[1]);
            float2 c0 = __bfloat1622float2(l2[0]), c1 = __bfloat1622float2(l2[1]);
            v0 += a0.x + c0.x; v1 += a0.y + c0.y;
            v2 += a1.x + c1.x; v3 += a1.y + c1.y;
        }
        v0 = fmaxf(v0, 0.f); v1 = fmaxf(v1, 0.f);
        v2 = fmaxf(v2, 0.f); v3 = fmaxf(v3, 0.f);
        __nv_bfloat16 h[4], l[4];
        split_bf16(v0, h[0], l[0]); split_bf16(v1, h[1], l[1]);
        split_bf16(v2, h[2], l[2]); split_bf16(v3, h[3], l[3]);
        *reinterpret_cast<uint2*>(outhi + go) = *reinterpret_cast<uint2*>(h);
        *reinterpret_cast<uint2*>(outlo + go) = *reinterpret_cast<uint2*>(l);
    }
}

// ---------------- GAP over hi/lo NHWC (permutation-invariant) ----------------
__global__ void gap_nhwc(const __nv_bfloat16* __restrict__ inhi,
                         const __nv_bfloat16* __restrict__ inlo, float* __restrict__ gap) {
    __shared__ float part[4][64];
    int b = blockIdx.x, t = threadIdx.x, ci = t & 63, q = t >> 6;
    const __nv_bfloat16* hb = inhi + (size_t)b * HW * 64;
    const __nv_bfloat16* lb = inlo + (size_t)b * HW * 64;
    float s = 0.0f;
    for (int px = q * 256; px < q * 256 + 256; px++) {
        size_t o = (size_t)px * 64 + ci;
        s += __bfloat162float(hb[o]) + __bfloat162float(lb[o]);
    }
    part[q][ci] = s;
    __syncthreads();
    if (t < 64) {
        // undo permutation: position t -> natural channel
        int p = t >> 1, gq = p >> 3, pw = p & 7;
        int k = (pw & 1) ? ((pw - 1) >> 1) + 4 : (pw >> 1);
        int nat = (gq * 8 + k) * 2 + (t & 1);
        gap[b * 64 + nat] =
            (part[0][t] + part[1][t] + part[2][t] + part[3][t]) * (1.0f / 1024.0f);
    }
}

// ---------------- resnet FC + masked merge into d_out ----------------
__global__ void fc_merge(const float* __restrict__ gap, const float* __restrict__ rfc,
                         const float* __restrict__ rfb, const int* __restrict__ flag,
                         float* out) {
    __shared__ float sg[64];
    int b = blockIdx.x, t = threadIdx.x;
    sg[t] = gap[b * 64 + t];
    __syncthreads();
    if (t < 10) {
        float a = rfb[t];
        #pragma unroll
        for (int k = 0; k < 64; k++) a = fmaf(sg[k], rfc[k * 10 + t], a);
        if (flag[b]) out[(size_t)b * 10 + t] = a;
    }
}

// ---------------- launcher ----------------
extern "C" void kernel_launch(void* const* d_in, const int* in_sizes, int n_in,
                              void* d_out, int out_size) {
    const float* x    = (const float*)d_in[0];
    const float* thr  = (const float*)d_in[1];
    const int*   lab  = (const int*)d_in[2];
    const float* lw1  = (const float*)d_in[3];
    const float* lb1  = (const float*)d_in[4];
    const float* lw2  = (const float*)d_in[5];
    const float* lb2  = (const float*)d_in[6];
    const float* lfc1 = (const float*)d_in[7];
    const float* lfb1 = (const float*)d_in[8];
    const float* lfc2 = (const float*)d_in[9];
    const float* lfb2 = (const float*)d_in[10];
    const float* lfc3 = (const float*)d_in[11];
    const float* lfb3 = (const float*)d_in[12];
    const float* rw0  = (const float*)d_in[13];
    const float* rb0  = (const float*)d_in[14];
    const float* rw1a = (const float*)d_in[15];
    const float* rb1a = (const float*)d_in[16];
    const float* rw1b = (const float*)d_in[17];
    const float* rb1b = (const float*)d_in[18];
    const float* rw2a = (const float*)d_in[19];
    const float* rb2a = (const float*)d_in[20];
    const float* rw2b = (const float*)d_in[21];
    const float* rb2b = (const float*)d_in[22];
    const float* rfc  = (const float*)d_in[23];
    const float* rfb  = (const float*)d_in[24];

    float* out  = (float*)d_out;
    float* conf = out + BATCH * 10;

    __nv_bfloat16 *Hhi, *Hlo, *Rhi, *Rlo, *Whi, *Wlo;
    float *gapb; int* flag;
    cudaGetSymbolAddress((void**)&Hhi,  g_Hhi);
    cudaGetSymbolAddress((void**)&Hlo,  g_Hlo);
    cudaGetSymbolAddress((void**)&Rhi,  g_Rhi);
    cudaGetSymbolAddress((void**)&Rlo,  g_Rlo);
    cudaGetSymbolAddress((void**)&Whi,  g_Whi);
    cudaGetSymbolAddress((void**)&Wlo,  g_Wlo);
    cudaGetSymbolAddress((void**)&gapb, g_gap);
    cudaGetSymbolAddress((void**)&flag, g_flag);

    cudaFuncSetAttribute(conv_mma, cudaFuncAttributeMaxDynamicSharedMemorySize, SMEM_BYTES);

    const int WL = 9 * 64 * 72;
    prep_w<<<(WL + 255) / 256, 256>>>(rw1a, Whi + 0 * WL, Wlo + 0 * WL);
    prep_w<<<(WL + 255) / 256, 256>>>(rw1b, Whi + 1 * WL, Wlo + 1 * WL);
    prep_w<<<(WL + 255) / 256, 256>>>(rw2a, Whi + 2 * WL, Wlo + 2 * WL);
    prep_w<<<(WL + 255) / 256, 256>>>(rw2b, Whi + 3 * WL, Wlo + 3 * WL);

    zero_conf<<<1, 128>>>(conf);

    // LeNet branch (fully fused)
    lenet_all<<<BATCH, 256>>>(x, lw1, lb1, lw2, lb2, lfc1, lfb1, lfc2, lfb2,
                              lfc3, lfb3, thr, lab, out, conf, flag);

    // ResNet branch (hi/lo bf16 NHWC activations, permuted ci-words)
    dim3 g0(BATCH, 4);
    conv0_k<<<g0, 256>>>(x, rw0, rb0, Hhi, Hlo);
    dim3 g(BATCH, 8);
    conv_mma<<<g, 256, SMEM_BYTES>>>(Hhi, Hlo, Whi + 0 * WL, Wlo + 0 * WL, rb1a,
                                     nullptr, nullptr, Rhi, Rlo);
    conv_mma<<<g, 256, SMEM_BYTES>>>(Rhi, Rlo, Whi + 1 * WL, Wlo + 1 * WL, rb1b,
                                     Hhi, Hlo, Hhi, Hlo);
    conv_mma<<<g, 256, SMEM_BYTES>>>(Hhi, Hlo, Whi + 2 * WL, Wlo + 2 * WL, rb2a,
                                     nullptr, nullptr, Rhi, Rlo);
    conv_mma<<<g, 256, SMEM_BYTES>>>(Rhi, Rlo, Whi + 3 * WL, Wlo + 3 * WL, rb2b,
                                     Hhi, Hlo, Hhi, Hlo);

    gap_nhwc<<<BATCH, 256>>>(Hhi, Hlo, gapb);
    fc_merge<<<BATCH, 64>>>(gapb, rfc, rfb, flag, out);
}

// round 8
// speedup vs baseline: 1.3967x; 1.3967x over previous
#include <cuda_runtime.h>
#include <cuda_bf16.h>
#include <cstdint>
#include <cstddef>

#define BATCH 1024
#define HW 1024   // 32*32

// ---------------- scratch (device globals; no allocs allowed) ----------------
__device__ __nv_bfloat16 g_Hhi[(size_t)BATCH * HW * 64];  // 128 MB each
__device__ __nv_bfloat16 g_Hlo[(size_t)BATCH * HW * 64];
__device__ __nv_bfloat16 g_Rhi[(size_t)BATCH * HW * 64];
__device__ __nv_bfloat16 g_Rlo[(size_t)BATCH * HW * 64];
__device__ __nv_bfloat16 g_Whi[4 * 9 * 64 * 72];
__device__ __nv_bfloat16 g_Wlo[4 * 9 * 64 * 72];
__device__ float g_gap[BATCH * 64];
__device__ int   g_flag[BATCH];

// ---------------- misc ----------------
__global__ void zero_conf(float* conf) {
    int t = threadIdx.x;
    if (t < 100) conf[t] = 0.0f;
}

// weight prep: OIHW fp32 [64][64][3][3] -> [s=9][co=64][ci pad 72] bf16 hi/lo
__global__ void prep_w(const float* __restrict__ w, __nv_bfloat16* __restrict__ whi,
                       __nv_bfloat16* __restrict__ wlo) {
    int idx = blockIdx.x * 256 + threadIdx.x;          // 9*64*72 = 41472
    if (idx >= 9 * 64 * 72) return;
    int s = idx / (64 * 72), rem = idx % (64 * 72), co = rem / 72, ci = rem % 72;
    float v = 0.0f;
    if (ci < 64) v = w[(co * 64 + ci) * 9 + s];
    __nv_bfloat16 h = __float2bfloat16(v);
    whi[idx] = h;
    wlo[idx] = __float2bfloat16(v - __bfloat162float(h));
}

// ---------------- fused LeNet: conv1+pool, conv2+pool, FCs, argmax/softmax/conf ----------------
__global__ __launch_bounds__(256) void lenet_all(
        const float* __restrict__ x, const float* __restrict__ w1, const float* __restrict__ b1,
        const float* __restrict__ w2, const float* __restrict__ b2,
        const float* __restrict__ fc1w, const float* __restrict__ fc1b,
        const float* __restrict__ fc2w, const float* __restrict__ fc2b,
        const float* __restrict__ fc3w, const float* __restrict__ fc3b,
        const float* __restrict__ thr_p, const int* __restrict__ labels,
        float* __restrict__ lenout, float* conf, int* __restrict__ flag) {
    __shared__ float sx[3 * 32 * 32];
    __shared__ float sw[2400];
    __shared__ float p1[1176];
    __shared__ float p2[400];
    __shared__ float h1[120];
    __shared__ float h2[84];
    __shared__ float lg[10];
    __shared__ float sb[16];
    int bid = blockIdx.x, t = threadIdx.x;
    const float* xb = x + (size_t)bid * 3072;
    for (int i = t; i < 3072; i += 256) sx[i] = xb[i];
    for (int i = t; i < 450; i += 256) sw[i] = w1[i];
    if (t < 6) sb[t] = b1[t];
    __syncthreads();
    for (int idx = t; idx < 6 * 14 * 14; idx += 256) {
        int c = idx / 196, py = (idx / 14) % 14, px = idx % 14;
        float m = -1e30f;
        #pragma unroll
        for (int dy = 0; dy < 2; dy++)
            #pragma unroll
            for (int dx = 0; dx < 2; dx++) {
                int y = 2 * py + dy, x0 = 2 * px + dx;
                float a = sb[c];
                for (int ci = 0; ci < 3; ci++)
                    #pragma unroll
                    for (int ky = 0; ky < 5; ky++)
                        #pragma unroll
                        for (int kx = 0; kx < 5; kx++)
                            a = fmaf(sx[ci * 1024 + (y + ky) * 32 + (x0 + kx)],
                                     sw[(c * 3 + ci) * 25 + ky * 5 + kx], a);
                m = fmaxf(m, a);
            }
        p1[idx] = fmaxf(m, 0.0f);
    }
    __syncthreads();
    for (int i = t; i < 2400; i += 256) sw[i] = w2[i];
    if (t < 16) sb[t] = b2[t];
    __syncthreads();
    for (int idx = t; idx < 400; idx += 256) {
        int c = idx / 25, py = (idx / 5) % 5, px = idx % 5;
        float m = -1e30f;
        #pragma unroll
        for (int dy = 0; dy < 2; dy++)
            #pragma unroll
            for (int dx = 0; dx < 2; dx++) {
                int y = 2 * py + dy, x0 = 2 * px + dx;
                float a = sb[c];
                for (int ci = 0; ci < 6; ci++)
                    #pragma unroll
                    for (int ky = 0; ky < 5; ky++)
                        #pragma unroll
                        for (int kx = 0; kx < 5; kx++)
                            a = fmaf(p1[ci * 196 + (y + ky) * 14 + (x0 + kx)],
                                     sw[(c * 6 + ci) * 25 + ky * 5 + kx], a);
                m = fmaxf(m, a);
            }
        p2[idx] = fmaxf(m, 0.0f);
    }
    __syncthreads();
    if (t < 120) {
        float a = fc1b[t];
        for (int k = 0; k < 400; k++) a = fmaf(p2[k], fc1w[k * 120 + t], a);
        h1[t] = fmaxf(a, 0.0f);
    }
    __syncthreads();
    if (t < 84) {
        float a = fc2b[t];
        for (int k = 0; k < 120; k++) a = fmaf(h1[k], fc2w[k * 84 + t], a);
        h2[t] = fmaxf(a, 0.0f);
    }
    __syncthreads();
    if (t < 10) {
        float a = fc3b[t];
        for (int k = 0; k < 84; k++) a = fmaf(h2[k], fc3w[k * 10 + t], a);
        lg[t] = a;
        lenout[(size_t)bid * 10 + t] = a;
    }
    __syncthreads();
    if (t == 0) {
        float m = lg[0]; int am = 0;
        #pragma unroll
        for (int i = 1; i < 10; i++) if (lg[i] > m) { m = lg[i]; am = i; }
        float p[10]; float s = 0.0f;
        #pragma unroll
        for (int i = 0; i < 10; i++) { p[i] = expf(lg[i] - m); s += p[i]; }
        float inv = 1.0f / s;
        float p0 = -1.0f, pp1 = -1.0f;
        #pragma unroll
        for (int i = 0; i < 10; i++) {
            float v = p[i] * inv;
            if (v > p0) { pp1 = p0; p0 = v; } else if (v > pp1) { pp1 = v; }
        }
        flag[bid] = ((p0 - pp1) <= thr_p[0]) ? 1 : 0;
        atomicAdd(&conf[labels[bid] * 10 + am], 1.0f);
    }
}

// ---------------- split helper ----------------
__device__ __forceinline__ void split_bf16(float v, __nv_bfloat16& h, __nv_bfloat16& l) {
    h = __float2bfloat16(v);
    l = __float2bfloat16(v - __bfloat162float(h));
}

// ---------------- ResNet conv0 (3->64, fp32 direct), hi/lo NHWC out + ReLU ----------------
__global__ __launch_bounds__(256, 2) void conv0_k(const float* __restrict__ x,
        const float* __restrict__ w, const float* __restrict__ bias,
        __nv_bfloat16* __restrict__ ohi, __nv_bfloat16* __restrict__ olo) {
    __shared__ __align__(16) float s_in[3 * 10 * 36];
    __shared__ float s_w[3 * 64 * 9];
    int b = blockIdx.x, row0 = blockIdx.y * 8;
    int t = threadIdx.x, warp = t >> 5, lane = t & 31;
    int r2 = lane >> 3, colg = lane & 7, cob = warp * 8;

    float acc[2][4][8];
    #pragma unroll
    for (int oc = 0; oc < 8; oc++) {
        float bv = bias[cob + oc];
        #pragma unroll
        for (int rr = 0; rr < 2; rr++)
            #pragma unroll
            for (int cc = 0; cc < 4; cc++) acc[rr][cc][oc] = bv;
    }
    const float* inb = x + (size_t)b * 3 * HW;
    for (int idx = t; idx < 3 * 340; idx += 256) {
        int kc = idx / 340, rem = idx % 340, r = rem / 34, c = rem % 34;
        int gr = row0 - 1 + r, gc = c - 1;
        float v = 0.0f;
        if ((unsigned)gr < 32u && (unsigned)gc < 32u)
            v = inb[(size_t)kc * HW + gr * 32 + gc];
        s_in[kc * 360 + r * 36 + c] = v;
    }
    for (int idx = t; idx < 3 * 576; idx += 256) {
        int kc = idx / 576, rem = idx % 576, co = rem / 9, k = rem % 9;
        s_w[idx] = w[((size_t)co * 3 + kc) * 9 + k];
    }
    __syncthreads();
    #pragma unroll
    for (int kc = 0; kc < 3; kc++) {
        float xin[4][6];
        const float* sbase = s_in + kc * 360 + (r2 * 2) * 36 + colg * 4;
        #pragma unroll
        for (int r = 0; r < 4; r++) {
            float4 a = *reinterpret_cast<const float4*>(sbase + r * 36);
            float2 bv = *reinterpret_cast<const float2*>(sbase + r * 36 + 4);
            xin[r][0] = a.x; xin[r][1] = a.y; xin[r][2] = a.z; xin[r][3] = a.w;
            xin[r][4] = bv.x; xin[r][5] = bv.y;
        }
        const float* wp = s_w + kc * 576 + cob * 9;
        #pragma unroll
        for (int oc = 0; oc < 8; oc++) {
            float w0 = wp[oc * 9], w1 = wp[oc * 9 + 1], w2 = wp[oc * 9 + 2];
            float w3 = wp[oc * 9 + 3], w4 = wp[oc * 9 + 4], w5 = wp[oc * 9 + 5];
            float w6 = wp[oc * 9 + 6], w7 = wp[oc * 9 + 7], w8 = wp[oc * 9 + 8];
            #pragma unroll
            for (int rr = 0; rr < 2; rr++)
                #pragma unroll
                for (int cc = 0; cc < 4; cc++) {
                    float a = acc[rr][cc][oc];
                    a = fmaf(xin[rr][cc],     w0, a);
                    a = fmaf(xin[rr][cc + 1], w1, a);
                    a = fmaf(xin[rr][cc + 2], w2, a);
                    a = fmaf(xin[rr + 1][cc],     w3, a);
                    a = fmaf(xin[rr + 1][cc + 1], w4, a);
                    a = fmaf(xin[rr + 1][cc + 2], w5, a);
                    a = fmaf(xin[rr + 2][cc],     w6, a);
                    a = fmaf(xin[rr + 2][cc + 1], w7, a);
                    a = fmaf(xin[rr + 2][cc + 2], w8, a);
                    acc[rr][cc][oc] = a;
                }
        }
    }
    size_t ob = (size_t)b * HW * 64;
    #pragma unroll
    for (int rr = 0; rr < 2; rr++)
        #pragma unroll
        for (int cc = 0; cc < 4; cc++) {
            int px = (row0 + r2 * 2 + rr) * 32 + colg * 4 + cc;
            __nv_bfloat16 hv[8], lv[8];
            #pragma unroll
            for (int oc = 0; oc < 8; oc++)
                split_bf16(fmaxf(acc[rr][cc][oc], 0.f), hv[oc], lv[oc]);
            *reinterpret_cast<uint4*>(ohi + ob + (size_t)px * 64 + cob) =
                *reinterpret_cast<uint4*>(hv);
            *reinterpret_cast<uint4*>(olo + ob + (size_t)px * 64 + cob) =
                *reinterpret_cast<uint4*>(lv);
        }
}

// ---------------- bf16x3 tensor-core 3x3 SAME conv, 64->64, hi/lo NHWC ----------------
__device__ __forceinline__ void mma_bf16(float* d, uint32_t a0, uint32_t a1, uint32_t a2,
                                         uint32_t a3, uint32_t b0, uint32_t b1) {
    asm volatile("mma.sync.aligned.m16n8k16.row.col.f32.bf16.bf16.f32 "
                 "{%0,%1,%2,%3}, {%4,%5,%6,%7}, {%8,%9}, {%0,%1,%2,%3};"
                 : "+f"(d[0]), "+f"(d[1]), "+f"(d[2]), "+f"(d[3])
                 : "r"(a0), "r"(a1), "r"(a2), "r"(a3), "r"(b0), "r"(b1));
}

#define IN_PITCH 36                 // words per px row (64 ci bf16 data + pad)
#define PLANE    7344               // 204 px (6 rows x 34 cols) * 36 words
#define WOFF     14688              // W buffers start (words)
#define WPLANE   2304               // 64 co * 36 words
#define SMEM_WORDS (WOFF + 2 * 2 * WPLANE)          // 23904
#define SMEM_BYTES (SMEM_WORDS * 4)                 // 95616

// Warp tiling: 8 warps = 4 px-groups (32 px) x 2 co-groups (32 co).
// Per warp: 2 m16 co-tiles x 4 n8 px-tiles. Balanced 32x32 minimizes smem bytes.
__global__ __launch_bounds__(256, 2) void conv_mma(
        const __nv_bfloat16* __restrict__ inhi,   // [B][1024][64]
        const __nv_bfloat16* __restrict__ inlo,
        const __nv_bfloat16* __restrict__ whi,    // [9][64][72]
        const __nv_bfloat16* __restrict__ wlo,
        const float* __restrict__ bias,
        const __nv_bfloat16* reshi, const __nv_bfloat16* reslo,
        __nv_bfloat16* __restrict__ outhi, __nv_bfloat16* __restrict__ outlo) {
    extern __shared__ uint32_t sm[];
    int b = blockIdx.x, g = blockIdx.y, r0 = g * 4;
    int t = threadIdx.x, lane = t & 31, warp = t >> 5;
    int cobase = (warp >> 2) * 32;           // 2 co-groups of 32
    int pxbase = (warp & 3) * 32;            // 4 px-groups of 32

    // ---- stage input tile via cp.async: 6 rows x 34 cols, hi+lo planes ----
    const __nv_bfloat16* hbase = inhi + (size_t)b * HW * 64;
    const __nv_bfloat16* lbase = inlo + (size_t)b * HW * 64;
    for (int idx = t; idx < 3264; idx += 256) {          // 2 planes * 204 px * 8 chunks
        int plane = idx >= 1632;
        int rem = idx - plane * 1632;
        int pxt = rem >> 3, ck = rem & 7;
        int rt = pxt / 34, ct = pxt % 34;
        int gr = r0 - 1 + rt, gc = ct - 1;
        int ok = ((unsigned)gr < 32u) && ((unsigned)gc < 32u);
        const __nv_bfloat16* base = plane ? lbase : hbase;
        const char* src = reinterpret_cast<const char*>(
            base + (ok ? ((size_t)(gr * 32 + gc)) * 64 + ck * 8 : 0));
        uint32_t dst = (uint32_t)__cvta_generic_to_shared(
            sm + plane * PLANE + pxt * IN_PITCH + ck * 4);
        int sz = ok ? 16 : 0;
        asm volatile("cp.async.ca.shared.global [%0], [%1], 16, %2;"
                     :: "r"(dst), "l"(src), "r"(sz));
    }

    // ---- cp.async weight staging, per shift, double buffered ----
    auto issueW = [&](int s, int buf) {
        for (int c = t; c < 1152; c += 256) {            // 2 planes * 576 16B chunks
            int plane = (c >= 576) ? 1 : 0;
            int cc = c - plane * 576;
            const char* src = reinterpret_cast<const char*>(plane ? wlo : whi)
                              + (size_t)s * 9216 + cc * 16;
            uint32_t dst = (uint32_t)__cvta_generic_to_shared(
                sm + WOFF + buf * (2 * WPLANE) + plane * WPLANE + cc * 4);
            asm volatile("cp.async.ca.shared.global [%0], [%1], 16;" :: "r"(dst), "l"(src));
        }
        asm volatile("cp.async.commit_group;" ::: "memory");
    };
    issueW(0, 0);

    // ---- accumulators + per-thread base offsets ----
    float acc[2][4][4];
    #pragma unroll
    for (int mt = 0; mt < 2; mt++) {
        float bv0 = bias[cobase + mt * 16 + (lane >> 2)];
        float bv1 = bias[cobase + mt * 16 + (lane >> 2) + 8];
        #pragma unroll
        for (int j = 0; j < 4; j++) {
            acc[mt][j][0] = bv0; acc[mt][j][1] = bv0;
            acc[mt][j][2] = bv1; acc[mt][j][3] = bv1;
        }
    }
    int bword[4];
    #pragma unroll
    for (int j = 0; j < 4; j++) {
        int p = pxbase + j * 8 + (lane >> 2);
        int r = p >> 5, c = p & 31;
        bword[j] = (r * 34 + c) * IN_PITCH + (lane & 3);
    }
    int awbase = (cobase + (lane >> 2)) * IN_PITCH + (lane & 3);

    // ---- main loop over 9 shifts ----
    for (int s = 0; s < 9; s++) {
        int buf = s & 1;
        asm volatile("cp.async.wait_group 0;" ::: "memory");
        __syncthreads();
        if (s < 8) issueW(s + 1, buf ^ 1);
        int ky = s / 3, kx = s - 3 * ky;
        int soff = (ky * 34 + kx) * IN_PITCH;
        const uint32_t* wh = sm + WOFF + buf * (2 * WPLANE);
        const uint32_t* wl = wh + WPLANE;
        const uint32_t* ih = sm;
        const uint32_t* il = sm + PLANE;
        #pragma unroll
        for (int q = 0; q < 4; q++) {
            uint32_t ah[2][4], al[2][4];
            #pragma unroll
            for (int mt = 0; mt < 2; mt++) {
                int aw = awbase + mt * (16 * IN_PITCH) + q * 8;
                ah[mt][0] = wh[aw];      ah[mt][1] = wh[aw + 8 * IN_PITCH];
                ah[mt][2] = wh[aw + 4];  ah[mt][3] = wh[aw + 8 * IN_PITCH + 4];
                al[mt][0] = wl[aw];      al[mt][1] = wl[aw + 8 * IN_PITCH];
                al[mt][2] = wl[aw + 4];  al[mt][3] = wl[aw + 8 * IN_PITCH + 4];
            }
            #pragma unroll
            for (int j = 0; j < 4; j++) {
                int bw = bword[j] + soff + q * 8;
                uint32_t bh0 = ih[bw], bh1 = ih[bw + 4];
                uint32_t bl0 = il[bw], bl1 = il[bw + 4];
                #pragma unroll
                for (int mt = 0; mt < 2; mt++) {
                    mma_bf16(acc[mt][j], ah[mt][0], ah[mt][1], ah[mt][2], ah[mt][3], bh0, bh1);
                    mma_bf16(acc[mt][j], ah[mt][0], ah[mt][1], ah[mt][2], ah[mt][3], bl0, bl1);
                    mma_bf16(acc[mt][j], al[mt][0], al[mt][1], al[mt][2], al[mt][3], bh0, bh1);
                }
            }
        }
    }

    // ---- epilogue: transpose through smem (fp32, pitch 68), then coalesced out ----
    float* smf = reinterpret_cast<float*>(sm);
    __syncthreads();
    {
        #pragma unroll
        for (int mt = 0; mt < 2; mt++) {
            int col = cobase + mt * 16 + (lane >> 2);
            #pragma unroll
            for (int j = 0; j < 4; j++) {
                int p0 = pxbase + j * 8 + (lane & 3) * 2;
                smf[p0 * 68 + col]            = acc[mt][j][0];
                smf[(p0 + 1) * 68 + col]      = acc[mt][j][1];
                smf[p0 * 68 + col + 8]        = acc[mt][j][2];
                smf[(p0 + 1) * 68 + col + 8]  = acc[mt][j][3];
            }
        }
    }
    __syncthreads();
    size_t obase = ((size_t)b * HW + g * 128) * 64;
    for (int idx = t; idx < 2048; idx += 256) {          // 128 px * 16 chunks of 4 co
        int px = idx >> 4, ck = idx & 15;
        float4 v = *reinterpret_cast<const float4*>(smf + px * 68 + ck * 4);
        size_t go = obase + (size_t)px * 64 + ck * 4;
        if (reshi) {
            uint2 rh = *reinterpret_cast<const uint2*>(reshi + go);
            uint2 rl = *reinterpret_cast<const uint2*>(reslo + go);
            const __nv_bfloat162* h2 = reinterpret_cast<const __nv_bfloat162*>(&rh);
            const __nv_bfloat162* l2 = reinterpret_cast<const __nv_bfloat162*>(&rl);
            float2 a0 = __bfloat1622float2(h2[0]), a1 = __bfloat1622float2(h2[1]);
            float2 c0 = __bfloat1622float2(l2[0]), c1 = __bfloat1622float2(l2[1]);
            v.x += a0.x + c0.x; v.y += a0.y + c0.y;
            v.z += a1.x + c1.x; v.w += a1.y + c1.y;
        }
        v.x = fmaxf(v.x, 0.f); v.y = fmaxf(v.y, 0.f);
        v.z = fmaxf(v.z, 0.f); v.w = fmaxf(v.w, 0.f);
        __nv_bfloat16 h[4], l[4];
        split_bf16(v.x, h[0], l[0]); split_bf16(v.y, h[1], l[1]);
        split_bf16(v.z, h[2], l[2]); split_bf16(v.w, h[3], l[3]);
        *reinterpret_cast<uint2*>(outhi + go) = *reinterpret_cast<uint2*>(h);
        *reinterpret_cast<uint2*>(outlo + go) = *reinterpret_cast<uint2*>(l);
    }
}

// ---------------- GAP over hi/lo NHWC ----------------
__global__ void gap_nhwc(const __nv_bfloat16* __restrict__ inhi,
                         const __nv_bfloat16* __restrict__ inlo, float* __restrict__ gap) {
    __shared__ float part[4][64];
    int b = blockIdx.x, t = threadIdx.x, ci = t & 63, q = t >> 6;
    const __nv_bfloat16* hb = inhi + (size_t)b * HW * 64;
    const __nv_bfloat16* lb = inlo + (size_t)b * HW * 64;
    float s = 0.0f;
    for (int px = q * 256; px < q * 256 + 256; px++) {
        size_t o = (size_t)px * 64 + ci;
        s += __bfloat162float(hb[o]) + __bfloat162float(lb[o]);
    }
    part[q][ci] = s;
    __syncthreads();
    if (t < 64)
        gap[b * 64 + t] = (part[0][t] + part[1][t] + part[2][t] + part[3][t]) * (1.0f / 1024.0f);
}

// ---------------- resnet FC + masked merge into d_out ----------------
__global__ void fc_merge(const float* __restrict__ gap, const float* __restrict__ rfc,
                         const float* __restrict__ rfb, const int* __restrict__ flag,
                         float* out) {
    __shared__ float sg[64];
    int b = blockIdx.x, t = threadIdx.x;
    sg[t] = gap[b * 64 + t];
    __syncthreads();
    if (t < 10) {
        float a = rfb[t];
        #pragma unroll
        for (int k = 0; k < 64; k++) a = fmaf(sg[k], rfc[k * 10 + t], a);
        if (flag[b]) out[(size_t)b * 10 + t] = a;
    }
}

// ---------------- launcher ----------------
extern "C" void kernel_launch(void* const* d_in, const int* in_sizes, int n_in,
                              void* d_out, int out_size) {
    const float* x    = (const float*)d_in[0];
    const float* thr  = (const float*)d_in[1];
    const int*   lab  = (const int*)d_in[2];
    const float* lw1  = (const float*)d_in[3];
    const float* lb1  = (const float*)d_in[4];
    const float* lw2  = (const float*)d_in[5];
    const float* lb2  = (const float*)d_in[6];
    const float* lfc1 = (const float*)d_in[7];
    const float* lfb1 = (const float*)d_in[8];
    const float* lfc2 = (const float*)d_in[9];
    const float* lfb2 = (const float*)d_in[10];
    const float* lfc3 = (const float*)d_in[11];
    const float* lfb3 = (const float*)d_in[12];
    const float* rw0  = (const float*)d_in[13];
    const float* rb0  = (const float*)d_in[14];
    const float* rw1a = (const float*)d_in[15];
    const float* rb1a = (const float*)d_in[16];
    const float* rw1b = (const float*)d_in[17];
    const float* rb1b = (const float*)d_in[18];
    const float* rw2a = (const float*)d_in[19];
    const float* rb2a = (const float*)d_in[20];
    const float* rw2b = (const float*)d_in[21];
    const float* rb2b = (const float*)d_in[22];
    const float* rfc  = (const float*)d_in[23];
    const float* rfb  = (const float*)d_in[24];

    float* out  = (float*)d_out;
    float* conf = out + BATCH * 10;

    __nv_bfloat16 *Hhi, *Hlo, *Rhi, *Rlo, *Whi, *Wlo;
    float *gapb; int* flag;
    cudaGetSymbolAddress((void**)&Hhi,  g_Hhi);
    cudaGetSymbolAddress((void**)&Hlo,  g_Hlo);
    cudaGetSymbolAddress((void**)&Rhi,  g_Rhi);
    cudaGetSymbolAddress((void**)&Rlo,  g_Rlo);
    cudaGetSymbolAddress((void**)&Whi,  g_Whi);
    cudaGetSymbolAddress((void**)&Wlo,  g_Wlo);
    cudaGetSymbolAddress((void**)&gapb, g_gap);
    cudaGetSymbolAddress((void**)&flag, g_flag);

    cudaFuncSetAttribute(conv_mma, cudaFuncAttributeMaxDynamicSharedMemorySize, SMEM_BYTES);

    const int WL = 9 * 64 * 72;
    prep_w<<<(WL + 255) / 256, 256>>>(rw1a, Whi + 0 * WL, Wlo + 0 * WL);
    prep_w<<<(WL + 255) / 256, 256>>>(rw1b, Whi + 1 * WL, Wlo + 1 * WL);
    prep_w<<<(WL + 255) / 256, 256>>>(rw2a, Whi + 2 * WL, Wlo + 2 * WL);
    prep_w<<<(WL + 255) / 256, 256>>>(rw2b, Whi + 3 * WL, Wlo + 3 * WL);

    zero_conf<<<1, 128>>>(conf);

    // LeNet branch (fully fused)
    lenet_all<<<BATCH, 256>>>(x, lw1, lb1, lw2, lb2, lfc1, lfb1, lfc2, lfb2,
                              lfc3, lfb3, thr, lab, out, conf, flag);

    // ResNet branch (hi/lo bf16 NHWC activations)
    dim3 g0(BATCH, 4);
    conv0_k<<<g0, 256>>>(x, rw0, rb0, Hhi, Hlo);
    dim3 g(BATCH, 8);
    conv_mma<<<g, 256, SMEM_BYTES>>>(Hhi, Hlo, Whi + 0 * WL, Wlo + 0 * WL, rb1a,
                                     nullptr, nullptr, Rhi, Rlo);
    conv_mma<<<g, 256, SMEM_BYTES>>>(Rhi, Rlo, Whi + 1 * WL, Wlo + 1 * WL, rb1b,
                                     Hhi, Hlo, Hhi, Hlo);
    conv_mma<<<g, 256, SMEM_BYTES>>>(Hhi, Hlo, Whi + 2 * WL, Wlo + 2 * WL, rb2a,
                                     nullptr, nullptr, Rhi, Rlo);
    conv_mma<<<g, 256, SMEM_BYTES>>>(Rhi, Rlo, Whi + 3 * WL, Wlo + 3 * WL, rb2b,
                                     Hhi, Hlo, Hhi, Hlo);

    gap_nhwc<<<BATCH, 256>>>(Hhi, Hlo, gapb);
    fc_merge<<<BATCH, 64>>>(gapb, rfc, rfb, flag, out);
}